// round 1
// baseline (speedup 1.0000x reference)
#include <cuda_runtime.h>
#include <cstdint>

#define NN    10000
#define NF    512
#define NH    32
#define NC    16
#define EMAX  360000

// ---- scratch (static device globals; no allocation allowed) ----
__device__ float g_xw1[NN * NH];     // x @ W1
__device__ float g_h  [NN * NH];     // relu(A_hat @ xw1)
__device__ float g_hw2[NN * NC];     // h @ W2
__device__ float g_z  [NN * NC];     // A_hat @ hw2
__device__ int   g_counts[NN];
__device__ int   g_rowstart[NN + 1];
__device__ int   g_cursor[NN];
__device__ int   g_col[EMAX];
__device__ float g_val[EMAX];

// 0) zero per-row edge counters
__global__ void k_init_counts() {
    int i = blockIdx.x * blockDim.x + threadIdx.x;
    if (i < NN) g_counts[i] = 0;
}

// 1) histogram edges by dst
__global__ void k_hist(const int* __restrict__ dst, int E) {
    int e = blockIdx.x * blockDim.x + threadIdx.x;
    if (e < E) atomicAdd(&g_counts[dst[e]], 1);
}

// 2) exclusive scan of counts -> rowstart (single block, 1024 x 10 items)
__global__ void k_scan() {
    __shared__ int sums[1024];
    const int t = threadIdx.x;
    int loc[10];
    int s = 0;
#pragma unroll
    for (int j = 0; j < 10; j++) {
        int i = t * 10 + j;
        int c = (i < NN) ? g_counts[i] : 0;
        loc[j] = s;
        s += c;
    }
    sums[t] = s;
    __syncthreads();
    for (int off = 1; off < 1024; off <<= 1) {
        int v = (t >= off) ? sums[t - off] : 0;
        __syncthreads();
        sums[t] += v;
        __syncthreads();
    }
    int base = (t > 0) ? sums[t - 1] : 0;
#pragma unroll
    for (int j = 0; j < 10; j++) {
        int i = t * 10 + j;
        if (i < NN) {
            int off = base + loc[j];
            g_rowstart[i] = off;
            g_cursor[i]   = off;
        }
    }
    if (t == 1023) g_rowstart[NN] = sums[1023];
}

// 3) scatter edges into CSR (col = src, val = weight)
__global__ void k_scatter(const int* __restrict__ src, const int* __restrict__ dst,
                          const float* __restrict__ w, int E) {
    int e = blockIdx.x * blockDim.x + threadIdx.x;
    if (e < E) {
        int d = dst[e];
        int p = atomicAdd(&g_cursor[d], 1);
        g_col[p] = src[e];
        g_val[p] = w[e];
    }
}

// 4) xw1 = x @ W1  (tile: 64 rows x 32 cols, kc=32, 256 threads, 2x4 microtile)
__global__ void k_gemm1(const float* __restrict__ x, const float* __restrict__ W1) {
    __shared__ float xs[64][36];
    __shared__ float ws[32][36];
    const int tid = threadIdx.x;
    const int tx  = tid & 7;
    const int ty  = tid >> 3;
    const int row0 = blockIdx.x * 64;

    float acc[2][4] = {};

    for (int k0 = 0; k0 < NF; k0 += 32) {
#pragma unroll
        for (int j = 0; j < 2; j++) {
            int f  = tid + 256 * j;
            int r  = f >> 3;
            int kq = f & 7;
            int gr = row0 + r;
            float4 v = make_float4(0.f, 0.f, 0.f, 0.f);
            if (gr < NN) v = *(const float4*)&x[(size_t)gr * NF + k0 + kq * 4];
            *(float4*)&xs[r][kq * 4] = v;
        }
        {
            int r  = tid >> 3;
            int kq = tid & 7;
            *(float4*)&ws[r][kq * 4] = *(const float4*)&W1[(k0 + r) * NH + kq * 4];
        }
        __syncthreads();
#pragma unroll
        for (int kk = 0; kk < 32; kk++) {
            float a0 = xs[ty * 2 + 0][kk];
            float a1 = xs[ty * 2 + 1][kk];
            float4 b = *(float4*)&ws[kk][tx * 4];
            acc[0][0] += a0 * b.x; acc[0][1] += a0 * b.y;
            acc[0][2] += a0 * b.z; acc[0][3] += a0 * b.w;
            acc[1][0] += a1 * b.x; acc[1][1] += a1 * b.y;
            acc[1][2] += a1 * b.z; acc[1][3] += a1 * b.w;
        }
        __syncthreads();
    }
#pragma unroll
    for (int i = 0; i < 2; i++) {
        int gr = row0 + ty * 2 + i;
        if (gr < NN) {
            float4 o = make_float4(acc[i][0], acc[i][1], acc[i][2], acc[i][3]);
            *(float4*)&g_xw1[gr * NH + tx * 4] = o;
        }
    }
}

// 5) h = relu(A_hat @ xw1) -- warp per dst row, gather, no float atomics
__global__ void k_spmm1() {
    int warp = (blockIdx.x * blockDim.x + threadIdx.x) >> 5;
    int l = threadIdx.x & 31;
    if (warp >= NN) return;
    int start = g_rowstart[warp];
    int end   = g_rowstart[warp + 1];
    float acc = 0.f;
    for (int base = start; base < end; base += 32) {
        int idx = base + l;
        int s = 0; float w = 0.f;
        if (idx < end) { s = g_col[idx]; w = g_val[idx]; }
        int cnt = min(32, end - base);
        for (int i = 0; i < cnt; i++) {
            int   si = __shfl_sync(0xffffffffu, s, i);
            float wi = __shfl_sync(0xffffffffu, w, i);
            acc += wi * g_xw1[si * NH + l];
        }
    }
    g_h[warp * NH + l] = fmaxf(acc, 0.f);
}

// 6) hw2 = h @ W2  (thread per row)
__global__ void k_gemm2(const float* __restrict__ W2) {
    __shared__ float w2s[NH * NC];
    const int tid = threadIdx.x;
    for (int i = tid; i < NH * NC; i += blockDim.x) w2s[i] = W2[i];
    __syncthreads();
    int row = blockIdx.x * blockDim.x + tid;
    if (row >= NN) return;
    float acc[NC] = {};
#pragma unroll
    for (int l = 0; l < NH; l++) {
        float hv = g_h[row * NH + l];
#pragma unroll
        for (int c = 0; c < NC; c++) acc[c] += hv * w2s[l * NC + c];
    }
#pragma unroll
    for (int q = 0; q < NC; q += 4) {
        float4 o = make_float4(acc[q], acc[q + 1], acc[q + 2], acc[q + 3]);
        *(float4*)&g_hw2[row * NC + q] = o;
    }
}

// 7) z = A_hat @ hw2 -- warp per row, lanes 0..15 carry features (16..31 shadow)
__global__ void k_spmm2() {
    int warp = (blockIdx.x * blockDim.x + threadIdx.x) >> 5;
    int l = threadIdx.x & 31;
    if (warp >= NN) return;
    int f = l & 15;
    int start = g_rowstart[warp];
    int end   = g_rowstart[warp + 1];
    float acc = 0.f;
    for (int base = start; base < end; base += 32) {
        int idx = base + l;
        int s = 0; float w = 0.f;
        if (idx < end) { s = g_col[idx]; w = g_val[idx]; }
        int cnt = min(32, end - base);
        for (int i = 0; i < cnt; i++) {
            int   si = __shfl_sync(0xffffffffu, s, i);
            float wi = __shfl_sync(0xffffffffu, w, i);
            acc += wi * g_hw2[si * NC + f];
        }
    }
    if (l < 16) g_z[warp * NC + l] = acc;
}

// 8) out = sigmoid(z @ z^T)  64x64 tile per block, 256 threads, 4x4 microtile
__device__ __forceinline__ float sigmoidf(float v) {
    return __fdividef(1.f, 1.f + __expf(-v));
}

__global__ void k_decode(float* __restrict__ out) {
    __shared__ float zr[NC][64];
    __shared__ float zc[NC][64];
    const int tid = threadIdx.x;
    const int r0 = blockIdx.y * 64;
    const int c0 = blockIdx.x * 64;
    {
        int row = tid >> 2;
        int kq  = tid & 3;
        int gr = r0 + row;
        float4 v = (gr < NN) ? *(const float4*)&g_z[gr * NC + kq * 4]
                             : make_float4(0.f, 0.f, 0.f, 0.f);
        zr[kq * 4 + 0][row] = v.x; zr[kq * 4 + 1][row] = v.y;
        zr[kq * 4 + 2][row] = v.z; zr[kq * 4 + 3][row] = v.w;
        int gc = c0 + row;
        v = (gc < NN) ? *(const float4*)&g_z[gc * NC + kq * 4]
                      : make_float4(0.f, 0.f, 0.f, 0.f);
        zc[kq * 4 + 0][row] = v.x; zc[kq * 4 + 1][row] = v.y;
        zc[kq * 4 + 2][row] = v.z; zc[kq * 4 + 3][row] = v.w;
    }
    __syncthreads();

    const int tx = tid & 15;
    const int ty = tid >> 4;
    float acc[4][4] = {};
#pragma unroll
    for (int k = 0; k < NC; k++) {
        float4 a = *(float4*)&zr[k][ty * 4];
        float4 b = *(float4*)&zc[k][tx * 4];
        acc[0][0] += a.x * b.x; acc[0][1] += a.x * b.y; acc[0][2] += a.x * b.z; acc[0][3] += a.x * b.w;
        acc[1][0] += a.y * b.x; acc[1][1] += a.y * b.y; acc[1][2] += a.y * b.z; acc[1][3] += a.y * b.w;
        acc[2][0] += a.z * b.x; acc[2][1] += a.z * b.y; acc[2][2] += a.z * b.z; acc[2][3] += a.z * b.w;
        acc[3][0] += a.w * b.x; acc[3][1] += a.w * b.y; acc[3][2] += a.w * b.z; acc[3][3] += a.w * b.w;
    }
    int gc = c0 + tx * 4;
    if (gc < NN) {
#pragma unroll
        for (int i = 0; i < 4; i++) {
            int gr = r0 + ty * 4 + i;
            if (gr < NN) {
                float4 o = make_float4(sigmoidf(acc[i][0]), sigmoidf(acc[i][1]),
                                       sigmoidf(acc[i][2]), sigmoidf(acc[i][3]));
                *(float4*)&out[(size_t)gr * NN + gc] = o;
            }
        }
    }
}

extern "C" void kernel_launch(void* const* d_in, const int* in_sizes, int n_in,
                              void* d_out, int out_size) {
    const float* x   = (const float*)d_in[0];   // [10000, 512]
    const float* W1  = (const float*)d_in[1];   // [512, 32]
    const float* W2  = (const float*)d_in[2];   // [32, 16]
    const float* ew  = (const float*)d_in[3];   // [E]
    const int*   src = (const int*)d_in[4];     // [E]
    const int*   dst = (const int*)d_in[5];     // [E]
    float* out = (float*)d_out;
    const int E = in_sizes[3];

    const int eb = (E + 255) / 256;

    k_init_counts<<<(NN + 255) / 256, 256>>>();
    k_hist<<<eb, 256>>>(dst, E);
    k_scan<<<1, 1024>>>();
    k_scatter<<<eb, 256>>>(src, dst, ew, E);

    k_gemm1<<<(NN + 63) / 64, 256>>>(x, W1);
    k_spmm1<<<(NN * 32 + 255) / 256, 256>>>();
    k_gemm2<<<(NN + 255) / 256, 256>>>(W2);
    k_spmm2<<<(NN * 32 + 255) / 256, 256>>>();

    dim3 grid((NN + 63) / 64, (NN + 63) / 64);
    k_decode<<<grid, 256>>>(out);
}